// round 9
// baseline (speedup 1.0000x reference)
#include <cuda_runtime.h>
#include <cuda_fp16.h>
#include <cstdint>

// Problem constants
#define B_SZ 4096
#define MAX_LEN 128
#define VOCAB 50000
#define EMB_D 300
#define REP_D 600
#define HID 1000
#define NCLS 5

#define KPAD 640      // 600 padded to 20 chunks of 32
#define NPAD 1024     // 1000 padded to 16 tiles of 64
#define BK 32
#define NCHUNK (KPAD / BK)       // 20
#define CONV_BLKS ((KPAD / 32) * (NPAD / 32))   // 20*32 = 640

// ---------------------------------------------------------------------------
// Scratch (no cudaMalloc allowed)
// ---------------------------------------------------------------------------
__device__ __align__(128) __half g_emb[VOCAB * EMB_D];   // fp16 table (30 MB)
__device__ __align__(128) __half g_a[B_SZ * KPAD];       // rep fp16 [4096,640]
__device__ __align__(128) __half g_b[NPAD * KPAD];       // W1^T fp16 [1024,640]

// ---------------------------------------------------------------------------
// PTX helpers (family-portable: ldmatrix / mma.sync / cp.async)
// ---------------------------------------------------------------------------
__device__ __forceinline__ uint32_t smem_u32(const void* p) {
    uint32_t a;
    asm("{ .reg .u64 t; cvta.to.shared.u64 t, %1; cvt.u32.u64 %0, t; }"
        : "=r"(a) : "l"(p));
    return a;
}

__device__ __forceinline__ void cp_async16(uint32_t smem_dst, const void* gmem_src) {
    asm volatile("cp.async.ca.shared.global [%0], [%1], 16;"
                 :: "r"(smem_dst), "l"(gmem_src));
}
#define CP_COMMIT() asm volatile("cp.async.commit_group;" ::: "memory")
#define CP_WAIT(n)  asm volatile("cp.async.wait_group %0;" :: "n"(n) : "memory")

__device__ __forceinline__ void ldsm4(uint32_t* r, uint32_t addr) {
    asm volatile("ldmatrix.sync.aligned.m8n8.x4.shared.b16 {%0,%1,%2,%3}, [%4];"
                 : "=r"(r[0]), "=r"(r[1]), "=r"(r[2]), "=r"(r[3]) : "r"(addr));
}

__device__ __forceinline__ void mma16816(float* c, const uint32_t* a,
                                         uint32_t b0, uint32_t b1) {
    asm volatile(
        "mma.sync.aligned.m16n8k16.row.col.f32.f16.f16.f32 "
        "{%0,%1,%2,%3}, {%4,%5,%6,%7}, {%8,%9}, {%0,%1,%2,%3};"
        : "+f"(c[0]), "+f"(c[1]), "+f"(c[2]), "+f"(c[3])
        : "r"(a[0]), "r"(a[1]), "r"(a[2]), "r"(a[3]), "r"(b0), "r"(b1));
}

// ---------------------------------------------------------------------------
// emb table fp32 -> fp16 (grid-stride, DRAM-bound ~11us)
// ---------------------------------------------------------------------------
#define EMB_Q (VOCAB * EMB_D / 4)   // 3,750,000 float4
__global__ void __launch_bounds__(256) conv_emb_kernel(const float* __restrict__ emb) {
    const int i = blockIdx.x * blockDim.x + threadIdx.x;
    if (i < EMB_Q) {
        const float4 v = __ldg(&((const float4*)emb)[i]);
        __half2 p0(__float2half_rn(v.x), __float2half_rn(v.y));
        __half2 p1(__float2half_rn(v.z), __float2half_rn(v.w));
        *(uint2*)&g_emb[i * 4] = make_uint2(*(uint32_t*)&p0, *(uint32_t*)&p1);
    }
}

// ---------------------------------------------------------------------------
// Hybrid kernel: blocks [0, B_SZ) pool one batch row each (fp16 gather);
// blocks [B_SZ, ...) transpose-convert one 32x32 tile of W1 to fp16.
// lengths in [1,127]: raw word[1]==0 <=> int64 layout.
// ---------------------------------------------------------------------------
__global__ void __launch_bounds__(80) pool_conv_kernel(
    const void* __restrict__ xv, const void* __restrict__ lenv,
    const float* __restrict__ b2, const float* __restrict__ W1,
    float* __restrict__ out)
{
    __shared__ __align__(16) char sm[32 * 33 * 4];
    const int tid = threadIdx.x;

    if (blockIdx.x >= B_SZ) {
        // ---- W1 convert: 32x32 tile transpose, fp32 -> fp16 ----
        float* tile = (float*)sm;               // [32][33]
        const int cb = blockIdx.x - B_SZ;
        const int kb = (cb % (KPAD / 32)) * 32;
        const int nb = (cb / (KPAD / 32)) * 32;
        for (int i = tid; i < 1024; i += 80) {
            const int kk = i >> 5, nn = i & 31;
            const int k = kb + kk, n = nb + nn;
            tile[kk * 33 + nn] =
                (k < REP_D && n < HID) ? __ldg(&W1[(long)k * HID + n]) : 0.0f;
        }
        __syncthreads();
        for (int i = tid; i < 1024; i += 80) {
            const int nn = i >> 5, kk = i & 31;
            g_b[(long)(nb + nn) * KPAD + kb + kk] =
                __float2half_rn(tile[kk * 33 + nn]);
        }
        return;
    }

    // ---- pooling ----
    int* idx_s = (int*)sm;
    const int b = blockIdx.x;
    const int is64 = (((const unsigned*)lenv)[1] == 0u);

    int len;
    if (is64) {
        len = (int)((const long long*)lenv)[b];
        for (int i = tid; i < len; i += 80)
            idx_s[i] = (int)((const long long*)xv)[(long)b * MAX_LEN + i];
    } else {
        len = ((const int*)lenv)[b];
        for (int i = tid; i < len; i += 80)
            idx_s[i] = ((const int*)xv)[(long)b * MAX_LEN + i];
    }
    __syncthreads();

    const long rowb = (long)b * KPAD;

    // out init: out[b][c] = b2[c]; mma accumulates atomically afterwards
    if (tid < NCLS)
        out[(long)b * NCLS + tid] = __ldg(&b2[tid]);

    if (tid >= 75) {
        // zero K padding cols 600..639 (5 threads x 8 halves)
        const int d0 = REP_D + (tid - 75) * 8;
        *(uint4*)&g_a[rowb + d0] = make_uint4(0u, 0u, 0u, 0u);
        return;
    }

    // thread owns 4 dims: one 8B (half4) gather per token
    float s0 = 0.f, s1 = 0.f, s2 = 0.f, s3 = 0.f;
    float m0 = -3.402823466e38f, m1 = m0, m2 = m0, m3 = m0;
#pragma unroll 8
    for (int t = 0; t < len; ++t) {
        const uint2 raw = __ldg((const uint2*)&g_emb[(long)idx_s[t] * EMB_D + 4 * tid]);
        const float2 v01 = __half22float2(*(const __half2*)&raw.x);
        const float2 v23 = __half22float2(*(const __half2*)&raw.y);
        s0 += v01.x; s1 += v01.y; s2 += v23.x; s3 += v23.y;
        m0 = fmaxf(m0, v01.x); m1 = fmaxf(m1, v01.y);
        m2 = fmaxf(m2, v23.x); m3 = fmaxf(m3, v23.y);
    }
    const float inv = 1.0f / (float)len;

    const int d = 4 * tid;
    {
        __half2 p0(__float2half_rn(s0 * inv), __float2half_rn(s1 * inv));
        __half2 p1(__float2half_rn(s2 * inv), __float2half_rn(s3 * inv));
        *(uint2*)&g_a[rowb + d] = make_uint2(*(uint32_t*)&p0, *(uint32_t*)&p1);
    }
    {
        __half2 p0(__float2half_rn(m0), __float2half_rn(m1));
        __half2 p1(__float2half_rn(m2), __float2half_rn(m3));
        *(uint2*)&g_a[rowb + EMB_D + d] = make_uint2(*(uint32_t*)&p0, *(uint32_t*)&p1);
    }
}

// ---------------------------------------------------------------------------
// Fused GEMM1 (fp16 via mma.sync) + bias + ReLU + GEMM2.
// CTA tile M=128,N=64; 8 warps (4m x 2n), warp tile 32x32; grid 512 CTAs.
// BK=32, 20 chunks, double-buffered stages of [A(128x32), B(64x32)].
// ---------------------------------------------------------------------------
#define LDSH 40                       // halves per smem row (32 + 8 pad)
#define TILE_A (128 * LDSH * 2)       // 10240
#define TILE_BB (64 * LDSH * 2)       // 5120
#define STAGE_B (TILE_A + TILE_BB)    // 15360
#define SMEM_BYTES (2 * STAGE_B)      // 30720

__device__ __forceinline__ void fill_stage(
    uint32_t sbase, int tid, int kc,
    const __half* ga, const __half* gb)
{
#pragma unroll
    for (int i = 0; i < 2; ++i) {
        const int e = tid + i * 256;
        const int row = e >> 2, seg = e & 3;
        const uint32_t so = (uint32_t)(row * LDSH + seg * 8) * 2;
        cp_async16(sbase + so, ga + (long)row * KPAD + kc + seg * 8);
    }
    {
        const int row = tid >> 2, seg = tid & 3;
        const uint32_t so = (uint32_t)(row * LDSH + seg * 8) * 2;
        cp_async16(sbase + TILE_A + so, gb + (long)row * KPAD + kc + seg * 8);
    }
}

__global__ void __launch_bounds__(256, 3) mma_kernel(
    const float* __restrict__ b1, const float* __restrict__ W2,
    float* __restrict__ out)
{
    extern __shared__ __align__(128) char smem[];
    const uint32_t sb = smem_u32(smem);
    const int tid  = threadIdx.x;
    const int wid  = tid >> 5;
    const int lane = tid & 31;
    const int warp_m = wid >> 1;      // 0..3
    const int warp_n = wid & 1;       // 0..1
    const int n0 = blockIdx.x * 64;
    const int m0 = blockIdx.y * 128;

    const __half* ga = g_a + (long)m0 * KPAD;
    const __half* gb = g_b + (long)n0 * KPAD;

    float acc[2][4][4];
#pragma unroll
    for (int a = 0; a < 2; ++a)
#pragma unroll
        for (int b = 0; b < 4; ++b)
#pragma unroll
            for (int d = 0; d < 4; ++d) acc[a][b][d] = 0.0f;

    // ldmatrix per-lane address components (in halves)
    const int a_row16 = (lane & 7) + ((lane >> 3) & 1) * 8;
    const int a_koff  = (lane >> 4) * 8;
    const int b_n16   = (lane & 7) + (lane >> 4) * 8;
    const int b_koff  = ((lane >> 3) & 1) * 8;

    fill_stage(sb, tid, 0, ga, gb);
    CP_COMMIT();

    for (int c = 0; c < NCHUNK; ++c) {
        const uint32_t cur = sb + (uint32_t)(c & 1) * STAGE_B;

        if (c + 1 < NCHUNK) {
            fill_stage(sb + (uint32_t)((c + 1) & 1) * STAGE_B, tid,
                       (c + 1) * BK, ga, gb);
            CP_COMMIT();
            CP_WAIT(1);
        } else {
            CP_WAIT(0);
        }
        __syncthreads();

#pragma unroll
        for (int ks = 0; ks < BK / 16; ++ks) {
            const int k0 = ks * 16;
            uint32_t bh[4][2];
            uint32_t af[2][4];

#pragma unroll
            for (int nf2 = 0; nf2 < 2; ++nf2) {
                const uint32_t boff =
                    (uint32_t)((warp_n * 32 + nf2 * 16 + b_n16) * LDSH + k0 + b_koff) * 2;
                uint32_t r[4];
                ldsm4(r, cur + TILE_A + boff);
                bh[nf2 * 2 + 0][0] = r[0]; bh[nf2 * 2 + 0][1] = r[1];
                bh[nf2 * 2 + 1][0] = r[2]; bh[nf2 * 2 + 1][1] = r[3];
            }
#pragma unroll
            for (int mf = 0; mf < 2; ++mf)
                ldsm4(af[mf], cur +
                      (uint32_t)((warp_m * 32 + mf * 16 + a_row16) * LDSH + k0 + a_koff) * 2);
#pragma unroll
            for (int mf = 0; mf < 2; ++mf)
#pragma unroll
                for (int nf = 0; nf < 4; ++nf)
                    mma16816(acc[mf][nf], af[mf], bh[nf][0], bh[nf][1]);
        }
        __syncthreads();
    }

    // --- Fused epilogue: bias + relu + W2 dot + atomic accumulate ---
    float* w2s = (float*)(smem);            // 64*5 floats
    float* b1s = (float*)(smem + 1280);     // 64 floats
    for (int i = tid; i < 64 * NCLS; i += 256) {
        const int n = n0 + i / NCLS;
        w2s[i] = (n < HID) ? __ldg(&W2[(long)n * NCLS + (i % NCLS)]) : 0.0f;
    }
    if (tid < 64) {
        const int n = n0 + tid;
        b1s[tid] = (n < HID) ? __ldg(&b1[n]) : 0.0f;
    }
    __syncthreads();

#pragma unroll
    for (int mf = 0; mf < 2; ++mf) {
#pragma unroll
        for (int h = 0; h < 2; ++h) {
            const int m = m0 + warp_m * 32 + mf * 16 + (lane >> 2) + 8 * h;
            float p0 = 0.f, p1 = 0.f, p2 = 0.f, p3 = 0.f, p4 = 0.f;
#pragma unroll
            for (int nf = 0; nf < 4; ++nf) {
                const int nl = warp_n * 32 + nf * 8 + 2 * (lane & 3);
                const float v0 = fmaxf(acc[mf][nf][2 * h + 0] + b1s[nl], 0.0f);
                const float v1 = fmaxf(acc[mf][nf][2 * h + 1] + b1s[nl + 1], 0.0f);
                p0 += v0 * w2s[nl * NCLS + 0] + v1 * w2s[(nl + 1) * NCLS + 0];
                p1 += v0 * w2s[nl * NCLS + 1] + v1 * w2s[(nl + 1) * NCLS + 1];
                p2 += v0 * w2s[nl * NCLS + 2] + v1 * w2s[(nl + 1) * NCLS + 2];
                p3 += v0 * w2s[nl * NCLS + 3] + v1 * w2s[(nl + 1) * NCLS + 3];
                p4 += v0 * w2s[nl * NCLS + 4] + v1 * w2s[(nl + 1) * NCLS + 4];
            }
#pragma unroll
            for (int off = 1; off <= 2; off <<= 1) {
                p0 += __shfl_xor_sync(0xffffffffu, p0, off);
                p1 += __shfl_xor_sync(0xffffffffu, p1, off);
                p2 += __shfl_xor_sync(0xffffffffu, p2, off);
                p3 += __shfl_xor_sync(0xffffffffu, p3, off);
                p4 += __shfl_xor_sync(0xffffffffu, p4, off);
            }
            if ((lane & 3) == 0) {
                atomicAdd(&out[(long)m * NCLS + 0], p0);
                atomicAdd(&out[(long)m * NCLS + 1], p1);
                atomicAdd(&out[(long)m * NCLS + 2], p2);
                atomicAdd(&out[(long)m * NCLS + 3], p3);
                atomicAdd(&out[(long)m * NCLS + 4], p4);
            }
        }
    }
}

// ---------------------------------------------------------------------------
extern "C" void kernel_launch(void* const* d_in, const int* in_sizes, int n_in,
                              void* d_out, int out_size)
{
    const void*  x       = d_in[0];
    const void*  lengths = d_in[1];
    const float* emb     = (const float*)d_in[2];
    const float* W1      = (const float*)d_in[3];
    const float* b1      = (const float*)d_in[4];
    const float* W2      = (const float*)d_in[5];
    const float* b2      = (const float*)d_in[6];
    float* out = (float*)d_out;

    cudaFuncSetAttribute(mma_kernel, cudaFuncAttributeMaxDynamicSharedMemorySize,
                         (int)SMEM_BYTES);

    conv_emb_kernel<<<(EMB_Q + 255) / 256, 256>>>(emb);

    pool_conv_kernel<<<B_SZ + CONV_BLKS, 80>>>(x, lengths, b2, W1, out);

    dim3 g(NPAD / 64, B_SZ / 128);  // (16, 32)
    mma_kernel<<<g, 256, SMEM_BYTES>>>(b1, W2, out);
}

// round 10
// speedup vs baseline: 1.1971x; 1.1971x over previous
#include <cuda_runtime.h>
#include <cuda_fp16.h>
#include <cstdint>

// Problem constants
#define B_SZ 4096
#define MAX_LEN 128
#define EMB_D 300
#define REP_D 600
#define HID 1000
#define NCLS 5

#define KPAD 640      // 600 padded to 20 chunks of 32
#define NPAD 1024     // 1000 padded to 16 tiles of 64
#define BK 32
#define NCHUNK (KPAD / BK)       // 20
#define CONV_BLKS ((KPAD / 32) * (NPAD / 32))   // 20*32 = 640

// ---------------------------------------------------------------------------
// Scratch (no cudaMalloc allowed)
// ---------------------------------------------------------------------------
__device__ __align__(128) __half g_a[B_SZ * KPAD];   // rep fp16 [4096,640]
__device__ __align__(128) __half g_b[NPAD * KPAD];   // W1^T fp16 [1024,640]

// ---------------------------------------------------------------------------
// PTX helpers (family-portable: ldmatrix / mma.sync / cp.async)
// ---------------------------------------------------------------------------
__device__ __forceinline__ uint32_t smem_u32(const void* p) {
    uint32_t a;
    asm("{ .reg .u64 t; cvta.to.shared.u64 t, %1; cvt.u32.u64 %0, t; }"
        : "=r"(a) : "l"(p));
    return a;
}

__device__ __forceinline__ void cp_async16(uint32_t smem_dst, const void* gmem_src) {
    asm volatile("cp.async.ca.shared.global [%0], [%1], 16;"
                 :: "r"(smem_dst), "l"(gmem_src));
}
#define CP_COMMIT() asm volatile("cp.async.commit_group;" ::: "memory")
#define CP_WAIT(n)  asm volatile("cp.async.wait_group %0;" :: "n"(n) : "memory")

__device__ __forceinline__ void ldsm4(uint32_t* r, uint32_t addr) {
    asm volatile("ldmatrix.sync.aligned.m8n8.x4.shared.b16 {%0,%1,%2,%3}, [%4];"
                 : "=r"(r[0]), "=r"(r[1]), "=r"(r[2]), "=r"(r[3]) : "r"(addr));
}

__device__ __forceinline__ void mma16816(float* c, const uint32_t* a,
                                         uint32_t b0, uint32_t b1) {
    asm volatile(
        "mma.sync.aligned.m16n8k16.row.col.f32.f16.f16.f32 "
        "{%0,%1,%2,%3}, {%4,%5,%6,%7}, {%8,%9}, {%0,%1,%2,%3};"
        : "+f"(c[0]), "+f"(c[1]), "+f"(c[2]), "+f"(c[3])
        : "r"(a[0]), "r"(a[1]), "r"(a[2]), "r"(a[3]), "r"(b0), "r"(b1));
}

// ---------------------------------------------------------------------------
// Hybrid kernel: blocks [0, B_SZ) pool one batch row each (fp32 gather);
// blocks [B_SZ, ...) transpose-convert one 32x32 tile of W1 to fp16.
// lengths in [1,127]: raw word[1]==0 <=> int64 layout.
// ---------------------------------------------------------------------------
__global__ void __launch_bounds__(80) pool_conv_kernel(
    const void* __restrict__ xv, const void* __restrict__ lenv,
    const float* __restrict__ emb, const float* __restrict__ b2,
    const float* __restrict__ W1, float* __restrict__ out)
{
    __shared__ __align__(16) char sm[32 * 33 * 4];
    const int tid = threadIdx.x;

    if (blockIdx.x >= B_SZ) {
        // ---- W1 convert: 32x32 tile transpose, fp32 -> fp16 ----
        float* tile = (float*)sm;               // [32][33]
        const int cb = blockIdx.x - B_SZ;
        const int kb = (cb % (KPAD / 32)) * 32;
        const int nb = (cb / (KPAD / 32)) * 32;
        for (int i = tid; i < 1024; i += 80) {
            const int kk = i >> 5, nn = i & 31;
            const int k = kb + kk, n = nb + nn;
            tile[kk * 33 + nn] =
                (k < REP_D && n < HID) ? __ldg(&W1[(long)k * HID + n]) : 0.0f;
        }
        __syncthreads();
        for (int i = tid; i < 1024; i += 80) {
            const int nn = i >> 5, kk = i & 31;
            g_b[(long)(nb + nn) * KPAD + kb + kk] =
                __float2half_rn(tile[kk * 33 + nn]);
        }
        return;
    }

    // ---- pooling ----
    int* idx_s = (int*)sm;
    const int b = blockIdx.x;
    const int is64 = (((const unsigned*)lenv)[1] == 0u);

    int len;
    if (is64) {
        len = (int)((const long long*)lenv)[b];
        for (int i = tid; i < len; i += 80)
            idx_s[i] = (int)((const long long*)xv)[(long)b * MAX_LEN + i];
    } else {
        len = ((const int*)lenv)[b];
        for (int i = tid; i < len; i += 80)
            idx_s[i] = ((const int*)xv)[(long)b * MAX_LEN + i];
    }
    __syncthreads();

    const long rowb = (long)b * KPAD;

    // out init: out[b][c] = b2[c]; mma accumulates atomically afterwards
    if (tid < NCLS)
        out[(long)b * NCLS + tid] = __ldg(&b2[tid]);

    if (tid >= 75) {
        // zero K padding cols 600..639 (5 threads x 8 halves)
        const int d0 = REP_D + (tid - 75) * 8;
        *(uint4*)&g_a[rowb + d0] = make_uint4(0u, 0u, 0u, 0u);
        return;
    }

    const float4* base = (const float4*)emb;   // emb rows: 75 float4 each
    float4 s  = make_float4(0.f, 0.f, 0.f, 0.f);
    float4 mx = make_float4(-3.402823466e38f, -3.402823466e38f,
                            -3.402823466e38f, -3.402823466e38f);
#pragma unroll 4
    for (int t = 0; t < len; ++t) {
        const float4 v = __ldg(&base[(long)idx_s[t] * 75 + tid]);
        s.x += v.x; s.y += v.y; s.z += v.z; s.w += v.w;
        mx.x = fmaxf(mx.x, v.x); mx.y = fmaxf(mx.y, v.y);
        mx.z = fmaxf(mx.z, v.z); mx.w = fmaxf(mx.w, v.w);
    }
    const float inv = 1.0f / (float)len;

    const int d = 4 * tid;
    {
        __half2 p0(__float2half_rn(s.x * inv), __float2half_rn(s.y * inv));
        __half2 p1(__float2half_rn(s.z * inv), __float2half_rn(s.w * inv));
        *(uint2*)&g_a[rowb + d] = make_uint2(*(uint32_t*)&p0, *(uint32_t*)&p1);
    }
    {
        __half2 p0(__float2half_rn(mx.x), __float2half_rn(mx.y));
        __half2 p1(__float2half_rn(mx.z), __float2half_rn(mx.w));
        *(uint2*)&g_a[rowb + EMB_D + d] = make_uint2(*(uint32_t*)&p0, *(uint32_t*)&p1);
    }
}

// ---------------------------------------------------------------------------
// Fused GEMM1 (fp16 via mma.sync) + bias + ReLU + GEMM2.
// CTA tile M=128,N=64; 8 warps (4m x 2n), warp tile 32x32; grid 512 CTAs.
// BK=32, 20 chunks, double-buffered stages of [A(128x32), B(64x32)].
// ---------------------------------------------------------------------------
#define LDSH 40                       // halves per smem row (32 + 8 pad)
#define TILE_A (128 * LDSH * 2)       // 10240
#define TILE_BB (64 * LDSH * 2)       // 5120
#define STAGE_B (TILE_A + TILE_BB)    // 15360
#define SMEM_BYTES (2 * STAGE_B)      // 30720

__device__ __forceinline__ void fill_stage(
    uint32_t sbase, int tid, int kc,
    const __half* ga, const __half* gb)
{
#pragma unroll
    for (int i = 0; i < 2; ++i) {
        const int e = tid + i * 256;
        const int row = e >> 2, seg = e & 3;
        const uint32_t so = (uint32_t)(row * LDSH + seg * 8) * 2;
        cp_async16(sbase + so, ga + (long)row * KPAD + kc + seg * 8);
    }
    {
        const int row = tid >> 2, seg = tid & 3;
        const uint32_t so = (uint32_t)(row * LDSH + seg * 8) * 2;
        cp_async16(sbase + TILE_A + so, gb + (long)row * KPAD + kc + seg * 8);
    }
}

__global__ void __launch_bounds__(256, 3) mma_kernel(
    const float* __restrict__ b1, const float* __restrict__ W2,
    float* __restrict__ out)
{
    extern __shared__ __align__(128) char smem[];
    const uint32_t sb = smem_u32(smem);
    const int tid  = threadIdx.x;
    const int wid  = tid >> 5;
    const int lane = tid & 31;
    const int warp_m = wid >> 1;      // 0..3
    const int warp_n = wid & 1;       // 0..1
    const int n0 = blockIdx.x * 64;
    const int m0 = blockIdx.y * 128;

    const __half* ga = g_a + (long)m0 * KPAD;
    const __half* gb = g_b + (long)n0 * KPAD;

    float acc[2][4][4];
#pragma unroll
    for (int a = 0; a < 2; ++a)
#pragma unroll
        for (int b = 0; b < 4; ++b)
#pragma unroll
            for (int d = 0; d < 4; ++d) acc[a][b][d] = 0.0f;

    // ldmatrix per-lane address components (in halves)
    const int a_row16 = (lane & 7) + ((lane >> 3) & 1) * 8;
    const int a_koff  = (lane >> 4) * 8;
    const int b_n16   = (lane & 7) + (lane >> 4) * 8;
    const int b_koff  = ((lane >> 3) & 1) * 8;

    fill_stage(sb, tid, 0, ga, gb);
    CP_COMMIT();

    for (int c = 0; c < NCHUNK; ++c) {
        const uint32_t cur = sb + (uint32_t)(c & 1) * STAGE_B;

        if (c + 1 < NCHUNK) {
            fill_stage(sb + (uint32_t)((c + 1) & 1) * STAGE_B, tid,
                       (c + 1) * BK, ga, gb);
            CP_COMMIT();
            CP_WAIT(1);
        } else {
            CP_WAIT(0);
        }
        __syncthreads();

#pragma unroll
        for (int ks = 0; ks < BK / 16; ++ks) {
            const int k0 = ks * 16;
            uint32_t bh[4][2];
            uint32_t af[2][4];

#pragma unroll
            for (int nf2 = 0; nf2 < 2; ++nf2) {
                const uint32_t boff =
                    (uint32_t)((warp_n * 32 + nf2 * 16 + b_n16) * LDSH + k0 + b_koff) * 2;
                uint32_t r[4];
                ldsm4(r, cur + TILE_A + boff);
                bh[nf2 * 2 + 0][0] = r[0]; bh[nf2 * 2 + 0][1] = r[1];
                bh[nf2 * 2 + 1][0] = r[2]; bh[nf2 * 2 + 1][1] = r[3];
            }
#pragma unroll
            for (int mf = 0; mf < 2; ++mf)
                ldsm4(af[mf], cur +
                      (uint32_t)((warp_m * 32 + mf * 16 + a_row16) * LDSH + k0 + a_koff) * 2);
#pragma unroll
            for (int mf = 0; mf < 2; ++mf)
#pragma unroll
                for (int nf = 0; nf < 4; ++nf)
                    mma16816(acc[mf][nf], af[mf], bh[nf][0], bh[nf][1]);
        }
        __syncthreads();
    }

    // --- Fused epilogue: bias + relu + W2 dot + atomic accumulate ---
    float* w2s = (float*)(smem);            // 64*5 floats
    float* b1s = (float*)(smem + 1280);     // 64 floats
    for (int i = tid; i < 64 * NCLS; i += 256) {
        const int n = n0 + i / NCLS;
        w2s[i] = (n < HID) ? __ldg(&W2[(long)n * NCLS + (i % NCLS)]) : 0.0f;
    }
    if (tid < 64) {
        const int n = n0 + tid;
        b1s[tid] = (n < HID) ? __ldg(&b1[n]) : 0.0f;
    }
    __syncthreads();

#pragma unroll
    for (int mf = 0; mf < 2; ++mf) {
#pragma unroll
        for (int h = 0; h < 2; ++h) {
            const int m = m0 + warp_m * 32 + mf * 16 + (lane >> 2) + 8 * h;
            float p0 = 0.f, p1 = 0.f, p2 = 0.f, p3 = 0.f, p4 = 0.f;
#pragma unroll
            for (int nf = 0; nf < 4; ++nf) {
                const int nl = warp_n * 32 + nf * 8 + 2 * (lane & 3);
                const float v0 = fmaxf(acc[mf][nf][2 * h + 0] + b1s[nl], 0.0f);
                const float v1 = fmaxf(acc[mf][nf][2 * h + 1] + b1s[nl + 1], 0.0f);
                p0 += v0 * w2s[nl * NCLS + 0] + v1 * w2s[(nl + 1) * NCLS + 0];
                p1 += v0 * w2s[nl * NCLS + 1] + v1 * w2s[(nl + 1) * NCLS + 1];
                p2 += v0 * w2s[nl * NCLS + 2] + v1 * w2s[(nl + 1) * NCLS + 2];
                p3 += v0 * w2s[nl * NCLS + 3] + v1 * w2s[(nl + 1) * NCLS + 3];
                p4 += v0 * w2s[nl * NCLS + 4] + v1 * w2s[(nl + 1) * NCLS + 4];
            }
#pragma unroll
            for (int off = 1; off <= 2; off <<= 1) {
                p0 += __shfl_xor_sync(0xffffffffu, p0, off);
                p1 += __shfl_xor_sync(0xffffffffu, p1, off);
                p2 += __shfl_xor_sync(0xffffffffu, p2, off);
                p3 += __shfl_xor_sync(0xffffffffu, p3, off);
                p4 += __shfl_xor_sync(0xffffffffu, p4, off);
            }
            if ((lane & 3) == 0) {
                atomicAdd(&out[(long)m * NCLS + 0], p0);
                atomicAdd(&out[(long)m * NCLS + 1], p1);
                atomicAdd(&out[(long)m * NCLS + 2], p2);
                atomicAdd(&out[(long)m * NCLS + 3], p3);
                atomicAdd(&out[(long)m * NCLS + 4], p4);
            }
        }
    }
}

// ---------------------------------------------------------------------------
extern "C" void kernel_launch(void* const* d_in, const int* in_sizes, int n_in,
                              void* d_out, int out_size)
{
    const void*  x       = d_in[0];
    const void*  lengths = d_in[1];
    const float* emb     = (const float*)d_in[2];
    const float* W1      = (const float*)d_in[3];
    const float* b1      = (const float*)d_in[4];
    const float* W2      = (const float*)d_in[5];
    const float* b2      = (const float*)d_in[6];
    float* out = (float*)d_out;

    cudaFuncSetAttribute(mma_kernel, cudaFuncAttributeMaxDynamicSharedMemorySize,
                         (int)SMEM_BYTES);

    pool_conv_kernel<<<B_SZ + CONV_BLKS, 80>>>(x, lengths, emb, b2, W1, out);

    dim3 g(NPAD / 64, B_SZ / 128);  // (16, 32)
    mma_kernel<<<g, 256, SMEM_BYTES>>>(b1, W2, out);
}

// round 11
// speedup vs baseline: 1.5600x; 1.3032x over previous
#include <cuda_runtime.h>
#include <cuda_fp16.h>
#include <cstdint>

// Problem constants
#define B_SZ 4096
#define MAX_LEN 128
#define EMB_D 300
#define REP_D 600
#define HID 1000
#define NCLS 5

#define KPAD 640      // 600 padded to 10 chunks of 64
#define NPAD 1024     // 1000 padded to 8 tiles of 128
#define BK 64
#define NCHUNK (KPAD / BK)       // 10
#define CONV_BLKS ((KPAD / 32) * (NPAD / 32))   // 20*32 = 640

// ---------------------------------------------------------------------------
// Scratch (no cudaMalloc allowed)
// ---------------------------------------------------------------------------
__device__ __align__(128) __half g_a[B_SZ * KPAD];   // rep fp16 [4096,640]
__device__ __align__(128) __half g_b[NPAD * KPAD];   // W1^T fp16 [1024,640]

// ---------------------------------------------------------------------------
// PTX helpers (family-portable: ldmatrix / mma.sync / cp.async)
// ---------------------------------------------------------------------------
__device__ __forceinline__ uint32_t smem_u32(const void* p) {
    uint32_t a;
    asm("{ .reg .u64 t; cvta.to.shared.u64 t, %1; cvt.u32.u64 %0, t; }"
        : "=r"(a) : "l"(p));
    return a;
}

__device__ __forceinline__ void cp_async16(uint32_t smem_dst, const void* gmem_src) {
    asm volatile("cp.async.ca.shared.global [%0], [%1], 16;"
                 :: "r"(smem_dst), "l"(gmem_src));
}
#define CP_COMMIT() asm volatile("cp.async.commit_group;" ::: "memory")
#define CP_WAIT(n)  asm volatile("cp.async.wait_group %0;" :: "n"(n) : "memory")

__device__ __forceinline__ void ldsm4(uint32_t* r, uint32_t addr) {
    asm volatile("ldmatrix.sync.aligned.m8n8.x4.shared.b16 {%0,%1,%2,%3}, [%4];"
                 : "=r"(r[0]), "=r"(r[1]), "=r"(r[2]), "=r"(r[3]) : "r"(addr));
}

__device__ __forceinline__ void mma16816(float* c, const uint32_t* a,
                                         uint32_t b0, uint32_t b1) {
    asm volatile(
        "mma.sync.aligned.m16n8k16.row.col.f32.f16.f16.f32 "
        "{%0,%1,%2,%3}, {%4,%5,%6,%7}, {%8,%9}, {%0,%1,%2,%3};"
        : "+f"(c[0]), "+f"(c[1]), "+f"(c[2]), "+f"(c[3])
        : "r"(a[0]), "r"(a[1]), "r"(a[2]), "r"(a[3]), "r"(b0), "r"(b1));
}

// ---------------------------------------------------------------------------
// Hybrid kernel: blocks [0, B_SZ) pool one batch row each (fp32 gather);
// blocks [B_SZ, ...) transpose-convert one 32x32 tile of W1 to fp16.
// lengths in [1,127]: raw word[1]==0 <=> int64 layout.
// ---------------------------------------------------------------------------
__global__ void __launch_bounds__(80) pool_conv_kernel(
    const void* __restrict__ xv, const void* __restrict__ lenv,
    const float* __restrict__ emb, const float* __restrict__ b2,
    const float* __restrict__ W1, float* __restrict__ out)
{
    __shared__ __align__(16) char sm[32 * 33 * 4];
    const int tid = threadIdx.x;

    if (blockIdx.x >= B_SZ) {
        // ---- W1 convert: 32x32 tile transpose, fp32 -> fp16 ----
        float* tile = (float*)sm;               // [32][33]
        const int cb = blockIdx.x - B_SZ;
        const int kb = (cb % (KPAD / 32)) * 32;
        const int nb = (cb / (KPAD / 32)) * 32;
        for (int i = tid; i < 1024; i += 80) {
            const int kk = i >> 5, nn = i & 31;
            const int k = kb + kk, n = nb + nn;
            tile[kk * 33 + nn] =
                (k < REP_D && n < HID) ? __ldg(&W1[(long)k * HID + n]) : 0.0f;
        }
        __syncthreads();
        for (int i = tid; i < 1024; i += 80) {
            const int nn = i >> 5, kk = i & 31;
            g_b[(long)(nb + nn) * KPAD + kb + kk] =
                __float2half_rn(tile[kk * 33 + nn]);
        }
        return;
    }

    // ---- pooling ----
    int* idx_s = (int*)sm;
    const int b = blockIdx.x;
    const int is64 = (((const unsigned*)lenv)[1] == 0u);

    int len;
    if (is64) {
        len = (int)((const long long*)lenv)[b];
        for (int i = tid; i < len; i += 80)
            idx_s[i] = (int)((const long long*)xv)[(long)b * MAX_LEN + i];
    } else {
        len = ((const int*)lenv)[b];
        for (int i = tid; i < len; i += 80)
            idx_s[i] = ((const int*)xv)[(long)b * MAX_LEN + i];
    }
    __syncthreads();

    const long rowb = (long)b * KPAD;

    // out init: out[b][c] = b2[c]; mma accumulates atomically afterwards
    if (tid < NCLS)
        out[(long)b * NCLS + tid] = __ldg(&b2[tid]);

    if (tid >= 75) {
        // zero K padding cols 600..639 (5 threads x 8 halves)
        const int d0 = REP_D + (tid - 75) * 8;
        *(uint4*)&g_a[rowb + d0] = make_uint4(0u, 0u, 0u, 0u);
        return;
    }

    const float4* base = (const float4*)emb;   // emb rows: 75 float4 each
    float4 s  = make_float4(0.f, 0.f, 0.f, 0.f);
    float4 mx = make_float4(-3.402823466e38f, -3.402823466e38f,
                            -3.402823466e38f, -3.402823466e38f);
#pragma unroll 4
    for (int t = 0; t < len; ++t) {
        const float4 v = __ldg(&base[(long)idx_s[t] * 75 + tid]);
        s.x += v.x; s.y += v.y; s.z += v.z; s.w += v.w;
        mx.x = fmaxf(mx.x, v.x); mx.y = fmaxf(mx.y, v.y);
        mx.z = fmaxf(mx.z, v.z); mx.w = fmaxf(mx.w, v.w);
    }
    const float inv = 1.0f / (float)len;

    const int d = 4 * tid;
    {
        __half2 p0(__float2half_rn(s.x * inv), __float2half_rn(s.y * inv));
        __half2 p1(__float2half_rn(s.z * inv), __float2half_rn(s.w * inv));
        *(uint2*)&g_a[rowb + d] = make_uint2(*(uint32_t*)&p0, *(uint32_t*)&p1);
    }
    {
        __half2 p0(__float2half_rn(mx.x), __float2half_rn(mx.y));
        __half2 p1(__float2half_rn(mx.z), __float2half_rn(mx.w));
        *(uint2*)&g_a[rowb + EMB_D + d] = make_uint2(*(uint32_t*)&p0, *(uint32_t*)&p1);
    }
}

// ---------------------------------------------------------------------------
// Fused GEMM1 (fp16 via mma.sync) + bias + ReLU + GEMM2.
// CTA tile M=128,N=128; 8 warps (2m x 4n), warp tile 64x32; grid 256 CTAs.
// BK=64, 10 chunks, double-buffered; 4 unrolled ksteps between barriers.
// ---------------------------------------------------------------------------
#define LDSH 72                       // halves per smem row (64 + 8 pad)
#define TILE_T (128 * LDSH * 2)       // 18432 per tile
#define STAGE_B (2 * TILE_T)          // 36864: [A, B]
#define SMEM_BYTES (2 * STAGE_B)      // 73728

__device__ __forceinline__ void fill_stage(
    uint32_t sbase, int tid, int kc,
    const __half* ga, const __half* gb)
{
#pragma unroll
    for (int i = 0; i < 4; ++i) {
        const int e = tid + i * 256;
        const int row = e >> 3, seg = e & 7;
        const uint32_t so = (uint32_t)(row * LDSH + seg * 8) * 2;
        const long go = (long)row * KPAD + kc + seg * 8;
        cp_async16(sbase + so, ga + go);
        cp_async16(sbase + TILE_T + so, gb + go);
    }
}

__global__ void __launch_bounds__(256, 2) mma_kernel(
    const float* __restrict__ b1, const float* __restrict__ W2,
    float* __restrict__ out)
{
    extern __shared__ __align__(128) char smem[];
    const uint32_t sb = smem_u32(smem);
    const int tid  = threadIdx.x;
    const int wid  = tid >> 5;
    const int lane = tid & 31;
    const int warp_m = wid >> 2;      // 0..1
    const int warp_n = wid & 3;       // 0..3
    const int n0 = blockIdx.x * 128;
    const int m0 = blockIdx.y * 128;

    const __half* ga = g_a + (long)m0 * KPAD;
    const __half* gb = g_b + (long)n0 * KPAD;

    float acc[4][4][4];
#pragma unroll
    for (int a = 0; a < 4; ++a)
#pragma unroll
        for (int b = 0; b < 4; ++b)
#pragma unroll
            for (int d = 0; d < 4; ++d) acc[a][b][d] = 0.0f;

    // ldmatrix per-lane address components (in halves)
    const int a_row16 = (lane & 7) + ((lane >> 3) & 1) * 8;
    const int a_koff  = (lane >> 4) * 8;
    const int b_n16   = (lane & 7) + (lane >> 4) * 8;
    const int b_koff  = ((lane >> 3) & 1) * 8;

    fill_stage(sb, tid, 0, ga, gb);
    CP_COMMIT();

    for (int c = 0; c < NCHUNK; ++c) {
        const uint32_t cur = sb + (uint32_t)(c & 1) * STAGE_B;

        if (c + 1 < NCHUNK) {
            fill_stage(sb + (uint32_t)((c + 1) & 1) * STAGE_B, tid,
                       (c + 1) * BK, ga, gb);
            CP_COMMIT();
            CP_WAIT(1);
        } else {
            CP_WAIT(0);
        }
        __syncthreads();

#pragma unroll
        for (int ks = 0; ks < BK / 16; ++ks) {
            const int k0 = ks * 16;
            uint32_t bh[4][2];
            uint32_t af[4][4];

#pragma unroll
            for (int nf2 = 0; nf2 < 2; ++nf2) {
                const uint32_t boff =
                    (uint32_t)((warp_n * 32 + nf2 * 16 + b_n16) * LDSH + k0 + b_koff) * 2;
                uint32_t r[4];
                ldsm4(r, cur + TILE_T + boff);
                bh[nf2 * 2 + 0][0] = r[0]; bh[nf2 * 2 + 0][1] = r[1];
                bh[nf2 * 2 + 1][0] = r[2]; bh[nf2 * 2 + 1][1] = r[3];
            }
#pragma unroll
            for (int mf = 0; mf < 4; ++mf)
                ldsm4(af[mf], cur +
                      (uint32_t)((warp_m * 64 + mf * 16 + a_row16) * LDSH + k0 + a_koff) * 2);
#pragma unroll
            for (int mf = 0; mf < 4; ++mf)
#pragma unroll
                for (int nf = 0; nf < 4; ++nf)
                    mma16816(acc[mf][nf], af[mf], bh[nf][0], bh[nf][1]);
        }
        __syncthreads();
    }

    // --- Fused epilogue: bias + relu + W2 dot + atomic accumulate ---
    float* w2s = (float*)(smem);            // 128*5 floats
    float* b1s = (float*)(smem + 2560);     // 128 floats
    for (int i = tid; i < 128 * NCLS; i += 256) {
        const int n = n0 + i / NCLS;
        w2s[i] = (n < HID) ? __ldg(&W2[(long)n * NCLS + (i % NCLS)]) : 0.0f;
    }
    if (tid < 128) {
        const int n = n0 + tid;
        b1s[tid] = (n < HID) ? __ldg(&b1[n]) : 0.0f;
    }
    __syncthreads();

#pragma unroll
    for (int mf = 0; mf < 4; ++mf) {
#pragma unroll
        for (int h = 0; h < 2; ++h) {
            const int m = m0 + warp_m * 64 + mf * 16 + (lane >> 2) + 8 * h;
            float p0 = 0.f, p1 = 0.f, p2 = 0.f, p3 = 0.f, p4 = 0.f;
#pragma unroll
            for (int nf = 0; nf < 4; ++nf) {
                const int nl = warp_n * 32 + nf * 8 + 2 * (lane & 3);
                const float v0 = fmaxf(acc[mf][nf][2 * h + 0] + b1s[nl], 0.0f);
                const float v1 = fmaxf(acc[mf][nf][2 * h + 1] + b1s[nl + 1], 0.0f);
                p0 += v0 * w2s[nl * NCLS + 0] + v1 * w2s[(nl + 1) * NCLS + 0];
                p1 += v0 * w2s[nl * NCLS + 1] + v1 * w2s[(nl + 1) * NCLS + 1];
                p2 += v0 * w2s[nl * NCLS + 2] + v1 * w2s[(nl + 1) * NCLS + 2];
                p3 += v0 * w2s[nl * NCLS + 3] + v1 * w2s[(nl + 1) * NCLS + 3];
                p4 += v0 * w2s[nl * NCLS + 4] + v1 * w2s[(nl + 1) * NCLS + 4];
            }
#pragma unroll
            for (int off = 1; off <= 2; off <<= 1) {
                p0 += __shfl_xor_sync(0xffffffffu, p0, off);
                p1 += __shfl_xor_sync(0xffffffffu, p1, off);
                p2 += __shfl_xor_sync(0xffffffffu, p2, off);
                p3 += __shfl_xor_sync(0xffffffffu, p3, off);
                p4 += __shfl_xor_sync(0xffffffffu, p4, off);
            }
            if ((lane & 3) == 0) {
                atomicAdd(&out[(long)m * NCLS + 0], p0);
                atomicAdd(&out[(long)m * NCLS + 1], p1);
                atomicAdd(&out[(long)m * NCLS + 2], p2);
                atomicAdd(&out[(long)m * NCLS + 3], p3);
                atomicAdd(&out[(long)m * NCLS + 4], p4);
            }
        }
    }
}

// ---------------------------------------------------------------------------
extern "C" void kernel_launch(void* const* d_in, const int* in_sizes, int n_in,
                              void* d_out, int out_size)
{
    const void*  x       = d_in[0];
    const void*  lengths = d_in[1];
    const float* emb     = (const float*)d_in[2];
    const float* W1      = (const float*)d_in[3];
    const float* b1      = (const float*)d_in[4];
    const float* W2      = (const float*)d_in[5];
    const float* b2      = (const float*)d_in[6];
    float* out = (float*)d_out;

    cudaFuncSetAttribute(mma_kernel, cudaFuncAttributeMaxDynamicSharedMemorySize,
                         (int)SMEM_BYTES);

    pool_conv_kernel<<<B_SZ + CONV_BLKS, 80>>>(x, lengths, emb, b2, W1, out);

    dim3 g(NPAD / 128, B_SZ / 128);  // (8, 32)
    mma_kernel<<<g, 256, SMEM_BYTES>>>(b1, W2, out);
}